// round 5
// baseline (speedup 1.0000x reference)
#include <cuda_runtime.h>

#define N_NODES 50000
#define IN_F    256
#define OUT_F   64
#define ROWS_PER_BLK 32
#define MAX_E   800000

// Scratch (alloc-guard-safe __device__ globals):
// per-node messages miu*att and sigma*att^2 (12.8 MB each),
// plus int32-normalized edge indices (3.2 MB each).
__device__ __align__(16) float g_miu[N_NODES * OUT_F];
__device__ __align__(16) float g_sig[N_NODES * OUT_F];
__device__ int g_src[MAX_E];
__device__ int g_dst[MAX_E];
__device__ int g_is64;

// ---------------------------------------------------------------------------
// Dtype probe: the reference asks for int64 indices but default-JAX silently
// downgrades to int32. Detect which layout we actually received.
// Reads only 256 bytes (safe for either layout). Deterministic.
// ---------------------------------------------------------------------------
__global__ void probe_kernel(const void* __restrict__ esrc)
{
    const long long* p = (const long long*)esrc;
    int ok64 = 1;
    for (int i = 0; i < 32; i++) {
        long long v = p[i];
        if (v < 0 || v >= N_NODES) { ok64 = 0; break; }
    }
    g_is64 = ok64;
}

// Normalize indices to int32 scratch regardless of source dtype.
__global__ __launch_bounds__(256) void convert_kernel(
    const void* __restrict__ esrc, const void* __restrict__ edst, int E)
{
    const int i = blockIdx.x * 256 + threadIdx.x;
    if (i >= E) return;
    if (g_is64) {
        g_src[i] = (int)((const long long*)esrc)[i];
        g_dst[i] = (int)((const long long*)edst)[i];
    } else {
        g_src[i] = ((const int*)esrc)[i];
        g_dst[i] = ((const int*)edst)[i];
    }
}

// ---------------------------------------------------------------------------
// Kernel A: fused dual-GEMM + activations.
// Block = 256 threads handles 32 rows x 64 features.
//   tid & 63  -> output feature f ;  tid >> 6 -> row group (8 rows each)
// Feature tile staged in smem (32KB); smem reads broadcast across the warp.
// Weight reads coalesced and L1/L2 resident (64KB per matrix).
// ---------------------------------------------------------------------------
__global__ __launch_bounds__(256) void gemm_act_kernel(
    const float* __restrict__ feat,
    const float* __restrict__ wm,
    const float* __restrict__ ws)
{
    __shared__ float fs[ROWS_PER_BLK * IN_F];
    const int row0 = blockIdx.x * ROWS_PER_BLK;
    const int tid  = threadIdx.x;
    const int nrows = min(ROWS_PER_BLK, N_NODES - row0);

    {
        const float4* gf  = (const float4*)(feat + (size_t)row0 * IN_F);
        float4*       fs4 = (float4*)fs;
        const int total4  = nrows * (IN_F / 4);
        for (int i = tid; i < total4; i += 256) fs4[i] = gf[i];
    }
    __syncthreads();

    const int f  = tid & 63;
    const int rg = tid >> 6;   // 0..3

    float accm[8], accs[8];
#pragma unroll
    for (int r = 0; r < 8; r++) { accm[r] = 0.f; accs[r] = 0.f; }

    const float4* fs4 = (const float4*)fs;

    for (int k = 0; k < IN_F; k += 4) {
        const float wm0 = __ldg(&wm[(k + 0) * OUT_F + f]);
        const float wm1 = __ldg(&wm[(k + 1) * OUT_F + f]);
        const float wm2 = __ldg(&wm[(k + 2) * OUT_F + f]);
        const float wm3 = __ldg(&wm[(k + 3) * OUT_F + f]);
        const float ws0 = __ldg(&ws[(k + 0) * OUT_F + f]);
        const float ws1 = __ldg(&ws[(k + 1) * OUT_F + f]);
        const float ws2 = __ldg(&ws[(k + 2) * OUT_F + f]);
        const float ws3 = __ldg(&ws[(k + 3) * OUT_F + f]);
#pragma unroll
        for (int r = 0; r < 8; r++) {
            const float4 fv = fs4[(rg * 8 + r) * (IN_F / 4) + (k >> 2)];
            accm[r] = fmaf(fv.x, wm0, fmaf(fv.y, wm1, fmaf(fv.z, wm2, fmaf(fv.w, wm3, accm[r]))));
            accs[r] = fmaf(fv.x, ws0, fmaf(fv.y, ws1, fmaf(fv.z, ws2, fmaf(fv.w, ws3, accs[r]))));
        }
    }

#pragma unroll
    for (int r = 0; r < 8; r++) {
        const int row = row0 + rg * 8 + r;
        if (row < N_NODES) {
            const float m   = accm[r];
            const float mi  = (m > 0.f) ? m : (expf(m) - 1.f);   // ELU
            const float s   = (accs[r] > 0.f) ? accs[r] : 0.f;   // ReLU
            const float att = expf(-s);                          // GAMMA = 1
            g_miu[row * OUT_F + f] = mi * att;
            g_sig[row * OUT_F + f] = s * att * att;
        }
    }
}

// ---------------------------------------------------------------------------
// Kernel B: edge scatter. One warp per edge.
//   lanes 0..15  -> 16 float4 chunks of the miu message (64 floats)
//   lanes 16..31 -> 16 float4 chunks of the sigma message
// One red.global.add.v4.f32 per lane = 32 REDs/edge (4x fewer than scalar).
// ---------------------------------------------------------------------------
__global__ __launch_bounds__(256) void scatter_kernel(
    const float* __restrict__ a1,
    const float* __restrict__ a2,
    float*       __restrict__ out,
    int E)
{
    const int gt   = blockIdx.x * 256 + threadIdx.x;
    const int e    = gt >> 5;
    if (e >= E) return;
    const int lane = gt & 31;

    const int s = g_src[e];
    const int d = g_dst[e];
    if ((unsigned)s >= N_NODES || (unsigned)d >= N_NODES) return;  // fail soft, not IMA

    const float* srcbase;
    float*       dstbase;
    float        sc;
    int          c;
    if (lane < 16) {
        c       = lane;
        srcbase = g_miu + (size_t)s * OUT_F;
        sc      = __ldg(a1 + e);
        dstbase = out + (size_t)d * OUT_F;                 // miu_out block
    } else {
        c       = lane - 16;
        srcbase = g_sig + (size_t)s * OUT_F;
        sc      = __ldg(a2 + e);
        dstbase = out + ((size_t)N_NODES + d) * OUT_F;     // sigma_out block
    }

    float4 v = ((const float4*)srcbase)[c];
    v.x *= sc; v.y *= sc; v.z *= sc; v.w *= sc;

    float* p = dstbase + c * 4;
    asm volatile("red.global.add.v4.f32 [%0], {%1, %2, %3, %4};"
                 :: "l"(p), "f"(v.x), "f"(v.y), "f"(v.z), "f"(v.w)
                 : "memory");
}

// ---------------------------------------------------------------------------
// Inputs (metadata order): features, edge_src, edge_dst, adj1_vals, adj2_vals,
//                          weight_miu, weight_sigma
// Output: [miu_out (N*64) ; sigma_out (N*64)] flattened row-major.
// ---------------------------------------------------------------------------
extern "C" void kernel_launch(void* const* d_in, const int* in_sizes, int n_in,
                              void* d_out, int out_size)
{
    const float* feat = (const float*)d_in[0];
    const void*  esrc = d_in[1];
    const void*  edst = d_in[2];
    const float* a1   = (const float*)d_in[3];
    const float* a2   = (const float*)d_in[4];
    const float* wm   = (const float*)d_in[5];
    const float* ws   = (const float*)d_in[6];
    float*       out  = (float*)d_out;
    const int E = in_sizes[3];   // adj1_vals count == E, dtype-independent

    cudaMemsetAsync(d_out, 0, (size_t)out_size * sizeof(float), 0);

    probe_kernel<<<1, 1>>>(esrc);
    convert_kernel<<<(E + 255) / 256, 256>>>(esrc, edst, E);

    const int gblocks = (N_NODES + ROWS_PER_BLK - 1) / ROWS_PER_BLK;
    gemm_act_kernel<<<gblocks, 256>>>(feat, wm, ws);

    const long long threads = (long long)E * 32;
    const int sblocks = (int)((threads + 255) / 256);
    scatter_kernel<<<sblocks, 256>>>(a1, a2, out, E);
}